// round 9
// baseline (speedup 1.0000x reference)
#include <cuda_runtime.h>
#include <cstdint>

// sim[b,o] = sum_d |x[b,d] - c[o,d]|;  out[b,o] = beta[o] * (max(sim)*1.001 - sim[b,o])
// x[1024,512], centers[512,512], beta[512] fp32 -> out fp32 [1024,512].
// R9: 1024 CTAs (16x32 tiles, frag 2x2, 128 thr) -> 98.8% wave balance under the
// grid barrier + 7 warps/SMSP for latency hiding. Conflict-free float4 smem,
// packed f32x2 math, register prefetch double buffer, epilogue from registers.

#define BM 16
#define BN 32
#define KC 32
#define NQ (KC / 4)        // 8 float4 quads per chunk
#define W_DIST 1.001f

typedef unsigned long long u64;
#define ABSM 0x7FFFFFFF7FFFFFFFULL
#define NEG1 0xBF800000BF800000ULL   // packed {-1.0f,-1.0f}

__device__ int      g_max_bits = 0;   // sims > 0 -> int order == float order
__device__ unsigned g_count1   = 0;
__device__ unsigned g_count2   = 0;

__device__ __forceinline__ u64 addx2(u64 a, u64 b) {
    u64 r; asm("add.rn.f32x2 %0, %1, %2;" : "=l"(r) : "l"(a), "l"(b)); return r;
}
__device__ __forceinline__ u64 fma2(u64 a, u64 b, u64 c) {
    u64 r; asm("fma.rn.f32x2 %0, %1, %2, %3;" : "=l"(r) : "l"(a), "l"(b), "l"(c)); return r;
}

__global__ __launch_bounds__(128, 7) void rbf_fused_kernel(
    const float* __restrict__ x,
    const float* __restrict__ c,
    const float* __restrict__ beta,
    float* __restrict__ out,
    int DIN, int DOUT, int NTN, unsigned NB)
{
    // [buf][quad][row(+1 f4 pad)]: STS.128 fill hits banks 4(q+r) mod 32 (distinct
    // per 8-lane phase); LDS.128 b-reads are 16-consecutive rows (clean phases),
    // a-reads broadcast. All conflict-free.
    __shared__ float4 xs[2][NQ][BM + 1];   // 4.25 KB
    __shared__ float4 cs[2][NQ][BN + 1];   // 8.25 KB
    __shared__ float  wmax[4];
    __shared__ float  s_gm;

    const int tid = threadIdx.x;
    const int bid = blockIdx.x;
    const int bm = bid / NTN;
    const int bn = bid % NTN;
    const int tr = tid >> 4;           // 0..7  -> m = tr + 8*i (i<2)
    const int tc = tid & 15;           // 0..15 -> n = tc + 16*j (j<2)

    u64 acc[2][2];
#pragma unroll
    for (int i = 0; i < 2; i++)
#pragma unroll
        for (int j = 0; j < 2; j++) acc[i][j] = 0ULL;

    // fill mapping: x tile 16 rows x 8 quads = 128 f4 (1/thread);
    //               c tile 32 rows x 8 quads = 256 f4 (2/thread: rows fr, fr+16)
    const int fq = tid & 7;            // 0..7
    const int fr = tid >> 3;           // 0..15
    const int qpr = DIN / 4;
    const float4* xg0 = reinterpret_cast<const float4*>(x) + (size_t)(bm * BM + fr)      * qpr + fq;
    const float4* cg0 = reinterpret_cast<const float4*>(c) + (size_t)(bn * BN + fr)      * qpr + fq;
    const float4* cg1 = reinterpret_cast<const float4*>(c) + (size_t)(bn * BN + fr + 16) * qpr + fq;

    float4 vx0 = *xg0, vc0 = *cg0, vc1 = *cg1;

    // prologue: fill buffer 0
    xs[0][fq][fr]      = vx0;
    cs[0][fq][fr]      = vc0;
    cs[0][fq][fr + 16] = vc1;
    __syncthreads();

    const int nchunks = DIN / KC;      // 16
    for (int ch = 0; ch < nchunks; ch++) {
        const int pb = ch & 1;
        if (ch + 1 < nchunks) {        // register prefetch of next chunk
            const int off = (ch + 1) * NQ;
            vx0 = xg0[off];
            vc0 = cg0[off];
            vc1 = cg1[off];
        }

#pragma unroll
        for (int p2 = 0; p2 < NQ; p2++) {      // one float4 = 4 k-elements
            float4 xa[2], cb[2];
#pragma unroll
            for (int i = 0; i < 2; i++) xa[i] = xs[pb][p2][tr + 8 * i];
#pragma unroll
            for (int j = 0; j < 2; j++) cb[j] = cs[pb][p2][tc + 16 * j];
#pragma unroll
            for (int i = 0; i < 2; i++) {
                const u64* au = reinterpret_cast<const u64*>(&xa[i]);
#pragma unroll
                for (int j = 0; j < 2; j++) {
                    const u64* bu = reinterpret_cast<const u64*>(&cb[j]);
                    u64 d0 = fma2(bu[0], NEG1, au[0]) & ABSM;   // |x-c| packed (lo pair)
                    u64 d1 = fma2(bu[1], NEG1, au[1]) & ABSM;   // |x-c| packed (hi pair)
                    acc[i][j] = addx2(acc[i][j], d0);
                    acc[i][j] = addx2(acc[i][j], d1);
                }
            }
        }

        if (ch + 1 < nchunks) {        // store prefetched chunk into the other buffer
            const int nb = 1 - pb;
            xs[nb][fq][fr]      = vx0;
            cs[nb][fq][fr]      = vc0;
            cs[nb][fq][fr + 16] = vc1;
        }
        __syncthreads();
    }

    // ---- per-thread sim fragment + block max ----
    float s[2][2];
    float tmax = 0.0f;
#pragma unroll
    for (int i = 0; i < 2; i++)
#pragma unroll
        for (int j = 0; j < 2; j++) {
            float2 v = *reinterpret_cast<float2*>(&acc[i][j]);
            s[i][j] = v.x + v.y;
            tmax = fmaxf(tmax, s[i][j]);
        }
#pragma unroll
    for (int off = 16; off > 0; off >>= 1)
        tmax = fmaxf(tmax, __shfl_xor_sync(0xffffffffu, tmax, off));
    if ((tid & 31) == 0) wmax[tid >> 5] = tmax;
    __syncthreads();

    // beta load before the spin (latency hidden under the barrier wait)
    float bet[2];
#pragma unroll
    for (int j = 0; j < 2; j++) bet[j] = beta[bn * BN + tc + 16 * j];

    // ---- grid barrier (all 1024 CTAs co-resident: launch_bounds(128,7), 7*148=1036 >= 1024) ----
    if (tid == 0) {
        float bmx = fmaxf(fmaxf(wmax[0], wmax[1]), fmaxf(wmax[2], wmax[3]));
        atomicMax(&g_max_bits, __float_as_int(bmx));
        __threadfence();
        atomicAdd(&g_count1, 1u);
        while (*((volatile unsigned*)&g_count1) < NB) { __nanosleep(64); }
        __threadfence();
        s_gm = __int_as_float(*((volatile int*)&g_max_bits)) * W_DIST;
        unsigned old = atomicAdd(&g_count2, 1u);   // last consumer resets for next graph replay
        if (old == NB - 1u) {
            g_max_bits = 0;
            g_count1   = 0;
            g_count2   = 0;
        }
    }
    __syncthreads();
    const float gm = s_gm;

    // ---- epilogue from registers ----
#pragma unroll
    for (int i = 0; i < 2; i++) {
        const int row = bm * BM + tr + 8 * i;
        float* orow = out + (size_t)row * DOUT + bn * BN;
#pragma unroll
        for (int j = 0; j < 2; j++)
            orow[tc + 16 * j] = bet[j] * (gm - s[i][j]);
    }
}

extern "C" void kernel_launch(void* const* d_in, const int* in_sizes, int n_in,
                              void* d_out, int out_size)
{
    const float* x    = (const float*)d_in[0];
    const float* c    = (const float*)d_in[1];
    const float* beta = (const float*)d_in[2];
    float* out = (float*)d_out;

    const int DOUT = in_sizes[2];
    const int DIN  = in_sizes[1] / DOUT;
    const int B    = in_sizes[0] / DIN;

    const int NTN = DOUT / BN;                       // 16
    const unsigned NB = (unsigned)((B / BM) * NTN);  // 1024
    rbf_fused_kernel<<<NB, 128>>>(x, c, beta, out, DIN, DOUT, NTN, NB);
}

// round 11
// speedup vs baseline: 1.1375x; 1.1375x over previous
#include <cuda_runtime.h>
#include <cstdint>

// sim[b,o] = sum_d |x[b,d] - c[o,d]|;  out[b,o] = beta[o] * (max(sim)*1.001 - sim[b,o])
// x[1024,512], centers[512,512], beta[512] fp32 -> out fp32 [1024,512].
// R10: tile 32x64, frag 4x4, 128 thr, grid 256 -> LDS/scalar 0.125 (was 0.1875).
// Negated-x smem so the diff is a 2-source addx2 (no RF 3-operand pressure);
// abs as 32-bit LOP3-immediate. Conflict-free float4 smem, grid barrier, reg epilogue.

#define BM 32
#define BN 64
#define KC 32
#define NQ (KC / 4)        // 8 float4 quads per chunk
#define W_DIST 1.001f

typedef unsigned long long u64;

__device__ int      g_max_bits = 0;   // sims > 0 -> int order == float order
__device__ unsigned g_count1   = 0;
__device__ unsigned g_count2   = 0;

__device__ __forceinline__ u64 addx2(u64 a, u64 b) {
    u64 r; asm("add.rn.f32x2 %0, %1, %2;" : "=l"(r) : "l"(a), "l"(b)); return r;
}
__device__ __forceinline__ u64 abs2(u64 a) {   // clear both sign bits; imm-form LOP3 per half
    uint2 v = *reinterpret_cast<uint2*>(&a);
    v.x &= 0x7fffffffu;
    v.y &= 0x7fffffffu;
    return *reinterpret_cast<u64*>(&v);
}

__global__ __launch_bounds__(128, 2) void rbf_fused_kernel(
    const float* __restrict__ x,
    const float* __restrict__ c,
    const float* __restrict__ beta,
    float* __restrict__ out,
    int DIN, int DOUT, unsigned NB)
{
    // [buf][quad][row(+1 f4 pad)] — STS.128 fill and LDS.128 reads conflict-free.
    __shared__ float4 xs[2][NQ][BM + 1];   // holds NEGATED x
    __shared__ float4 cs[2][NQ][BN + 1];
    __shared__ float  wmax[4];
    __shared__ float  s_gm;

    const int tid = threadIdx.x;
    const int bm = blockIdx.y;
    const int bn = blockIdx.x;
    const int tr = tid >> 4;           // 0..7  -> m = tr + 8*i  (i<4)
    const int tc = tid & 15;           // 0..15 -> n = tc + 16*j (j<4)

    u64 acc[4][4];
#pragma unroll
    for (int i = 0; i < 4; i++)
#pragma unroll
        for (int j = 0; j < 4; j++) acc[i][j] = 0ULL;

    // fill mapping: x tile 32 rows x 8 quads = 256 f4 (2/thread);
    //               c tile 64 rows x 8 quads = 512 f4 (4/thread)
    const int fq = tid & 7;            // 0..7
    const int fr = tid >> 3;           // 0..15
    const int qpr = DIN / 4;
    const float4* xg0 = reinterpret_cast<const float4*>(x) + (size_t)(bm * BM + fr)      * qpr + fq;
    const float4* xg1 = reinterpret_cast<const float4*>(x) + (size_t)(bm * BM + fr + 16) * qpr + fq;
    const float4* cg0 = reinterpret_cast<const float4*>(c) + (size_t)(bn * BN + fr)      * qpr + fq;
    const float4* cg1 = reinterpret_cast<const float4*>(c) + (size_t)(bn * BN + fr + 16) * qpr + fq;
    const float4* cg2 = reinterpret_cast<const float4*>(c) + (size_t)(bn * BN + fr + 32) * qpr + fq;
    const float4* cg3 = reinterpret_cast<const float4*>(c) + (size_t)(bn * BN + fr + 48) * qpr + fq;

    float4 vx0 = *xg0, vx1 = *xg1;
    float4 vc0 = *cg0, vc1 = *cg1, vc2 = *cg2, vc3 = *cg3;

    // prologue: fill buffer 0 (x stored negated -> inner diff = c + (-x))
    xs[0][fq][fr]      = make_float4(-vx0.x, -vx0.y, -vx0.z, -vx0.w);
    xs[0][fq][fr + 16] = make_float4(-vx1.x, -vx1.y, -vx1.z, -vx1.w);
    cs[0][fq][fr]      = vc0;
    cs[0][fq][fr + 16] = vc1;
    cs[0][fq][fr + 32] = vc2;
    cs[0][fq][fr + 48] = vc3;
    __syncthreads();

    const int nchunks = DIN / KC;      // 16
    for (int ch = 0; ch < nchunks; ch++) {
        const int pb = ch & 1;
        if (ch + 1 < nchunks) {        // register prefetch of next chunk
            const int off = (ch + 1) * NQ;
            vx0 = xg0[off]; vx1 = xg1[off];
            vc0 = cg0[off]; vc1 = cg1[off]; vc2 = cg2[off]; vc3 = cg3[off];
        }

#pragma unroll
        for (int p2 = 0; p2 < NQ; p2++) {      // one float4 = 4 k-elements
            float4 xa[4], cb[4];
#pragma unroll
            for (int i = 0; i < 4; i++) xa[i] = xs[pb][p2][tr + 8 * i];
#pragma unroll
            for (int j = 0; j < 4; j++) cb[j] = cs[pb][p2][tc + 16 * j];
#pragma unroll
            for (int i = 0; i < 4; i++) {
                const u64* au = reinterpret_cast<const u64*>(&xa[i]);
#pragma unroll
                for (int j = 0; j < 4; j++) {
                    const u64* bu = reinterpret_cast<const u64*>(&cb[j]);
                    u64 d0 = abs2(addx2(bu[0], au[0]));   // |c - x| packed (lo pair)
                    u64 d1 = abs2(addx2(bu[1], au[1]));   // |c - x| packed (hi pair)
                    acc[i][j] = addx2(acc[i][j], d0);
                    acc[i][j] = addx2(acc[i][j], d1);
                }
            }
        }

        if (ch + 1 < nchunks) {        // store prefetched chunk into the other buffer
            const int nb = 1 - pb;
            xs[nb][fq][fr]      = make_float4(-vx0.x, -vx0.y, -vx0.z, -vx0.w);
            xs[nb][fq][fr + 16] = make_float4(-vx1.x, -vx1.y, -vx1.z, -vx1.w);
            cs[nb][fq][fr]      = vc0;
            cs[nb][fq][fr + 16] = vc1;
            cs[nb][fq][fr + 32] = vc2;
            cs[nb][fq][fr + 48] = vc3;
        }
        __syncthreads();
    }

    // ---- per-thread sim fragment + block max ----
    float s[4][4];
    float tmax = 0.0f;
#pragma unroll
    for (int i = 0; i < 4; i++)
#pragma unroll
        for (int j = 0; j < 4; j++) {
            float2 v = *reinterpret_cast<float2*>(&acc[i][j]);
            s[i][j] = v.x + v.y;
            tmax = fmaxf(tmax, s[i][j]);
        }
#pragma unroll
    for (int off = 16; off > 0; off >>= 1)
        tmax = fmaxf(tmax, __shfl_xor_sync(0xffffffffu, tmax, off));
    if ((tid & 31) == 0) wmax[tid >> 5] = tmax;
    __syncthreads();

    // beta load before the spin (latency hidden under barrier wait)
    float bet[4];
#pragma unroll
    for (int j = 0; j < 4; j++) bet[j] = beta[bn * BN + tc + 16 * j];

    // ---- grid barrier (all 256 CTAs co-resident: launch_bounds(128,2), 256 <= 2*148) ----
    if (tid == 0) {
        float bmx = fmaxf(fmaxf(wmax[0], wmax[1]), fmaxf(wmax[2], wmax[3]));
        atomicMax(&g_max_bits, __float_as_int(bmx));
        __threadfence();
        atomicAdd(&g_count1, 1u);
        while (*((volatile unsigned*)&g_count1) < NB) { __nanosleep(64); }
        __threadfence();
        s_gm = __int_as_float(*((volatile int*)&g_max_bits)) * W_DIST;
        unsigned old = atomicAdd(&g_count2, 1u);   // last consumer resets for next graph replay
        if (old == NB - 1u) {
            g_max_bits = 0;
            g_count1   = 0;
            g_count2   = 0;
        }
    }
    __syncthreads();
    const float gm = s_gm;

    // ---- epilogue from registers ----
#pragma unroll
    for (int i = 0; i < 4; i++) {
        const int row = bm * BM + tr + 8 * i;
        float* orow = out + (size_t)row * DOUT + bn * BN;
#pragma unroll
        for (int j = 0; j < 4; j++)
            orow[tc + 16 * j] = bet[j] * (gm - s[i][j]);
    }
}

extern "C" void kernel_launch(void* const* d_in, const int* in_sizes, int n_in,
                              void* d_out, int out_size)
{
    const float* x    = (const float*)d_in[0];
    const float* c    = (const float*)d_in[1];
    const float* beta = (const float*)d_in[2];
    float* out = (float*)d_out;

    const int DOUT = in_sizes[2];
    const int DIN  = in_sizes[1] / DOUT;
    const int B    = in_sizes[0] / DIN;

    dim3 grid(DOUT / BN, B / BM);            // 8 x 32 = 256
    const unsigned NB = grid.x * grid.y;
    rbf_fused_kernel<<<grid, 128>>>(x, c, beta, out, DIN, DOUT, NB);
}